// round 4
// baseline (speedup 1.0000x reference)
#include <cuda_runtime.h>
#include <math.h>

// MaxNormPooling2D: quaternion max-norm 2x2 pooling, stride 2, VALID.
// Inputs: x0..x3 each (B=16, H=128, W=128, C=64) fp32, NHWC.
// Output: concatenated (out0, out1, out2, out3), each (16, 64, 64, 64) fp32.
//
// Per (b, ho, wo, c): over the 4 window positions (dh,dw) in row-major
// order, pick the position with max sqrt(x0^2+x1^2+x2^2+x3^2) (first-max
// tie-break) and emit that position's 4 components.

#define B_  16
#define H_  128
#define W_  128
#define C_  64
#define HO_ 64
#define WO_ 64

// float4 granularity: 16 float4 groups per pixel channel dim (C=64/4)
#define C4_ 16
// total threads = B * HO * WO * C4 = 16*64*64*16 = 1,048,576
#define NTHREADS_TOTAL (B_ * HO_ * WO_ * C4_)

// per-component output size in float4 units: 16*64*64*64/4 = 1,048,576
#define OUT_COMP_F4 (B_ * HO_ * WO_ * C_ / 4)

__global__ __launch_bounds__(256) void maxnorm_pool_kernel(
    const float4* __restrict__ x0,
    const float4* __restrict__ x1,
    const float4* __restrict__ x2,
    const float4* __restrict__ x3,
    float4* __restrict__ out)
{
    int t = blockIdx.x * blockDim.x + threadIdx.x;
    if (t >= NTHREADS_TOTAL) return;

    int c4  = t & (C4_ - 1);
    int pix = t >> 4;             // b*HO*WO + ho*WO + wo
    int wo  = pix & (WO_ - 1);
    int ho  = (pix >> 6) & (HO_ - 1);
    int b   = pix >> 12;

    int h0 = ho << 1;
    int w0 = wo << 1;

    // input index in float4 units: ((b*H + h)*W + w)*C4 + c4
    // offsets for the 4 window positions (row-major: (0,0),(0,1),(1,0),(1,1))
    int base = ((b * H_ + h0) * W_ + w0) * C4_ + c4;
    int off[4];
    off[0] = base;
    off[1] = base + C4_;          // dw=1: +C floats = +16 float4
    off[2] = base + W_ * C4_;     // dh=1: +W*C floats
    off[3] = base + W_ * C4_ + C4_;

    // best norm per lane (norms are >= 0, so -1 guarantees p=0 wins first)
    float4 bn = make_float4(-1.f, -1.f, -1.f, -1.f);
    float4 o0, o1, o2, o3;

#pragma unroll
    for (int p = 0; p < 4; ++p) {
        float4 a0 = x0[off[p]];
        float4 a1 = x1[off[p]];
        float4 a2 = x2[off[p]];
        float4 a3 = x3[off[p]];

        // sequential sum order x0^2 + x1^2 + x2^2 + x3^2, then sqrt —
        // matches the reference's comparison domain for tie behavior.
        float nx = sqrtf(a0.x * a0.x + a1.x * a1.x + a2.x * a2.x + a3.x * a3.x);
        float ny = sqrtf(a0.y * a0.y + a1.y * a1.y + a2.y * a2.y + a3.y * a3.y);
        float nz = sqrtf(a0.z * a0.z + a1.z * a1.z + a2.z * a2.z + a3.z * a3.z);
        float nw = sqrtf(a0.w * a0.w + a1.w * a1.w + a2.w * a2.w + a3.w * a3.w);

        if (nx > bn.x) { bn.x = nx; o0.x = a0.x; o1.x = a1.x; o2.x = a2.x; o3.x = a3.x; }
        if (ny > bn.y) { bn.y = ny; o0.y = a0.y; o1.y = a1.y; o2.y = a2.y; o3.y = a3.y; }
        if (nz > bn.z) { bn.z = nz; o0.z = a0.z; o1.z = a1.z; o2.z = a2.z; o3.z = a3.z; }
        if (nw > bn.w) { bn.w = nw; o0.w = a0.w; o1.w = a1.w; o2.w = a2.w; o3.w = a3.w; }
    }

    int obase = pix * C4_ + c4;   // within one component, float4 units
    out[obase]                   = o0;
    out[obase + OUT_COMP_F4]     = o1;
    out[obase + 2 * OUT_COMP_F4] = o2;
    out[obase + 3 * OUT_COMP_F4] = o3;
}

extern "C" void kernel_launch(void* const* d_in, const int* in_sizes, int n_in,
                              void* d_out, int out_size)
{
    const float4* x0 = (const float4*)d_in[0];
    const float4* x1 = (const float4*)d_in[1];
    const float4* x2 = (const float4*)d_in[2];
    const float4* x3 = (const float4*)d_in[3];
    float4* out = (float4*)d_out;

    const int threads = 256;
    const int blocks  = NTHREADS_TOTAL / threads;  // 4096
    maxnorm_pool_kernel<<<blocks, threads>>>(x0, x1, x2, x3, out);
}